// round 10
// baseline (speedup 1.0000x reference)
#include <cuda_runtime.h>
#include <cuda_fp16.h>
#include <math.h>
#include <stdint.h>

#define VOCABN 96
#define DIM 1024
#define NH 16
#define HSZ 64
#define NL 8
#define BATCH 8
#define SEQ 1024
#define FFD 4096
#define MROWS (BATCH*SEQ)   // 8192
#define QKVLD (3*DIM)       // fused qkv row stride

// ---------------- scratch (device globals; no allocations allowed) ----------
__device__ float g_x[MROWS*DIM];                       // residual stream fp32
__device__ float g_y[MROWS*DIM];                       // proj/ff2 output fp32
__device__ float g_nll[MROWS];
__device__ __align__(16) __half g_xrh[MROWS*DIM];      // fp16 copy of x
__device__ __align__(16) __half g_qkv[(long long)MROWS*QKVLD];
__device__ __align__(16) __half g_oh[MROWS*DIM];       // attention out fp16
__device__ __align__(16) __half g_hh[(long long)MROWS*FFD];
__device__ __align__(16) __half g_wqkvT[(long long)NL*3*DIM*DIM];
__device__ __align__(16) __half g_woT[NL*DIM*DIM];
__device__ __align__(16) __half g_w1T[(long long)NL*DIM*FFD];
__device__ __align__(16) __half g_w2T[(long long)NL*FFD*DIM];

// ======================= fp16 mma.sync helpers ===============================
__device__ __forceinline__ void mma_f16(float* c, const uint32_t* a, const uint32_t* b) {
    asm volatile(
        "mma.sync.aligned.m16n8k16.row.col.f32.f16.f16.f32 "
        "{%0,%1,%2,%3}, {%4,%5,%6,%7}, {%8,%9}, {%0,%1,%2,%3};"
        : "+f"(c[0]), "+f"(c[1]), "+f"(c[2]), "+f"(c[3])
        : "r"(a[0]), "r"(a[1]), "r"(a[2]), "r"(a[3]),
          "r"(b[0]), "r"(b[1]));
}

__device__ __forceinline__ void ldm_x4(uint32_t* r, uint32_t addr) {
    asm volatile(
        "ldmatrix.sync.aligned.m8n8.x4.shared.b16 {%0,%1,%2,%3}, [%4];"
        : "=r"(r[0]), "=r"(r[1]), "=r"(r[2]), "=r"(r[3]) : "r"(addr));
}

__device__ __forceinline__ void ldm_x4t(uint32_t* r, uint32_t addr) {
    asm volatile(
        "ldmatrix.sync.aligned.m8n8.x4.trans.shared.b16 {%0,%1,%2,%3}, [%4];"
        : "=r"(r[0]), "=r"(r[1]), "=r"(r[2]), "=r"(r[3]) : "r"(addr));
}

__device__ __forceinline__ uint32_t smem_u32_of(const void* p) {
    uint32_t a;
    asm("{ .reg .u64 t; cvta.to.shared.u64 t, %1; cvt.u32.u64 %0, t; }"
        : "=r"(a) : "l"(p));
    return a;
}

__device__ __forceinline__ void cp16(uint32_t dst, const void* src) {
    asm volatile("cp.async.cg.shared.global [%0], [%1], 16;"
                 :: "r"(dst), "l"(src) : "memory");
}

__device__ __forceinline__ uint32_t pack_h2(float a, float b) {
    __half2 h = __floats2half2_rn(a, b);
    return *(uint32_t*)&h;
}

// ============ fp16 tensor GEMM: C[M,N] = A[M,K] @ B^T  (B stored [N,K]) =====
// CTA tile 128x128x64, 256 threads = 8 warps (2m x 4n), warp tile 64x32.
// 2-stage cp.async pipeline; fragments via ldmatrix; fp32 accumulate.
#define TBM 128
#define TBN 128
#define TBK 64            // 64 halfs = 4 k16 steps
#define SPADH 72          // smem row stride in halfs (144B: conflict-free phases)
#define GBUFH (128*SPADH) // halfs per tile
#define GSM_BYTES (2*2*GBUFH*2)   // 2 stages x (A+B) = 73728 bytes

__global__ void __launch_bounds__(256, 2)
gemm_mma(const __half* __restrict__ A, const __half* __restrict__ B,
         const float* __restrict__ bias, float* __restrict__ Cf,
         __half* __restrict__ Ch,
         int K, int lda, int ldb, int ldc, int relu)
{
    extern __shared__ __half smh[];
    const int tid  = threadIdx.x;
    const int wid  = tid >> 5;
    const int lane = tid & 31;
    const int g    = lane >> 2;
    const int tg   = lane & 3;
    const int wm   = wid >> 2;    // 0..1
    const int wn   = wid & 3;     // 0..3

    const int bm = blockIdx.y * TBM;
    const int bn = blockIdx.x * TBN;

    // cp.async: thread owns one 32-half chunk (64B) of one row
    const int r = tid >> 1;
    const int ho = (tid & 1) * 32;
    const int rowoff = r * SPADH + ho;

    const uint32_t smb = smem_u32_of(smh);
    const __half* ga = A + (size_t)(bm + r) * lda + ho;
    const __half* gb = B + (size_t)(bn + r) * ldb + ho;

    // ldmatrix per-lane offsets (halfs) relative to tile base
    const int arow = (wm * 64 + (lane & 15)) * SPADH + ((lane & 16) ? 8 : 0);
    const int brow = ((lane & 7) + ((lane & 16) ? 8 : 0)) * SPADH
                   + ((lane & 8) ? 8 : 0);

    float acc[4][4][4] = {};
    const int KT = K / TBK;

    auto issue = [&](int kt, int buf) {
        const __half* pa = ga + (size_t)kt * TBK;
        const __half* pb = gb + (size_t)kt * TBK;
        uint32_t da = smb + (uint32_t)(buf * 2 * GBUFH + rowoff) * 2;
        uint32_t db = da + GBUFH * 2;
        #pragma unroll
        for (int c = 0; c < 4; c++) {
            cp16(da + c * 16, pa + c * 8);
            cp16(db + c * 16, pb + c * 8);
        }
        asm volatile("cp.async.commit_group;" ::: "memory");
    };

    issue(0, 0);

    int buf = 0;
    for (int kt = 0; kt < KT; kt++) {
        asm volatile("cp.async.wait_group 0;" ::: "memory");
        __syncthreads();
        if (kt + 1 < KT) issue(kt + 1, buf ^ 1);

        const uint32_t abase = smb + (uint32_t)(buf * 2 * GBUFH + arow) * 2;
        const uint32_t bbase = smb + (uint32_t)(buf * 2 * GBUFH + GBUFH + brow) * 2;

        #pragma unroll
        for (int ks = 0; ks < 4; ks++) {          // k16 steps
            uint32_t af[4][4], bf[4][2];
            #pragma unroll
            for (int i = 0; i < 4; i++)
                ldm_x4(af[i], abase + (uint32_t)(i * 16 * SPADH + ks * 16) * 2);
            #pragma unroll
            for (int np = 0; np < 2; np++) {      // n 16-blocks within warp's 32
                uint32_t t4[4];
                ldm_x4(t4, bbase + (uint32_t)((wn * 32 + np * 16) * SPADH + ks * 16) * 2);
                bf[np * 2 + 0][0] = t4[0]; bf[np * 2 + 0][1] = t4[1];
                bf[np * 2 + 1][0] = t4[2]; bf[np * 2 + 1][1] = t4[3];
            }
            #pragma unroll
            for (int i = 0; i < 4; i++)
                #pragma unroll
                for (int j = 0; j < 4; j++)
                    mma_f16(acc[i][j], af[i], bf[j]);
        }
        buf ^= 1;
    }

    // epilogue: bias + relu; write fp16 (tensor consumers) or fp32 (residual)
    #pragma unroll
    for (int i = 0; i < 4; i++) {
        const int m0 = bm + wm * 64 + i * 16 + g;
        #pragma unroll
        for (int j = 0; j < 4; j++) {
            const int n0 = bn + wn * 32 + j * 8 + tg * 2;
            float2 v0 = make_float2(acc[i][j][0], acc[i][j][1]);
            float2 v1 = make_float2(acc[i][j][2], acc[i][j][3]);
            if (bias) {
                float2 bv = *(const float2*)(bias + n0);
                v0.x += bv.x; v0.y += bv.y;
                v1.x += bv.x; v1.y += bv.y;
            }
            if (relu) {
                v0.x = fmaxf(v0.x, 0.f); v0.y = fmaxf(v0.y, 0.f);
                v1.x = fmaxf(v1.x, 0.f); v1.y = fmaxf(v1.y, 0.f);
            }
            if (Ch) {
                *(uint32_t*)(Ch + (size_t)m0 * ldc + n0)       = pack_h2(v0.x, v0.y);
                *(uint32_t*)(Ch + (size_t)(m0 + 8) * ldc + n0) = pack_h2(v1.x, v1.y);
            } else {
                *(float2*)(Cf + (size_t)m0 * ldc + n0)       = v0;
                *(float2*)(Cf + (size_t)(m0 + 8) * ldc + n0) = v1;
            }
        }
    }
}

// ============ Flash attention (causal, online softmax, fp16 mma) ============
// grid = (16 q-tiles, B*NH). block = 128 threads (4 warps, 16 q-rows each).
#define FPADH 72
#define FA_SMEM ((3*64*FPADH + 4*16*FPADH) * 2)   // 36864 bytes

__global__ void __launch_bounds__(128, 4)
flash_kernel()
{
    extern __shared__ __half smh[];
    __half* Qs = smh;                   // [64][FPADH]
    __half* Ks = smh + 64 * FPADH;      // [64][FPADH]
    __half* Vs = smh + 2 * 64 * FPADH;  // [64][FPADH]
    __half* Ps = smh + 3 * 64 * FPADH;  // [4][16][FPADH]

    const int bh = blockIdx.y;
    const int b = bh >> 4, hh = bh & 15;
    const int qt = gridDim.x - 1 - blockIdx.x;   // heavy blocks first
    const int tid = threadIdx.x;
    const int wid = tid >> 5, lane = tid & 31;
    const int g = lane >> 2, tg = lane & 3;

    const __half* Qg = g_qkv + ((size_t)b * SEQ + qt * 64) * QKVLD + hh * HSZ;
    const __half* Kg = g_qkv + (size_t)b * SEQ * QKVLD + DIM + hh * HSZ;
    const __half* Vg = g_qkv + (size_t)b * SEQ * QKVLD + 2 * DIM + hh * HSZ;

    const uint32_t smb = smem_u32_of(smh);
    const uint32_t qs_b = smb;
    const uint32_t ks_b = smb + 64 * FPADH * 2;
    const uint32_t vs_b = smb + 2 * 64 * FPADH * 2;
    const uint32_t pw_b = smb + (3 * 64 + wid * 16) * FPADH * 2;

    // load Q tile (64 rows x 64 halfs)
    {
        const int r = tid >> 1, c0 = (tid & 1) * 32;
        const __half* src = Qg + (size_t)r * QKVLD + c0;
        __half* dst = Qs + r * FPADH + c0;
        #pragma unroll
        for (int c = 0; c < 32; c += 8)
            *(uint4*)(dst + c) = *(const uint4*)(src + c);
    }

    float m0 = -1e30f, m1 = -1e30f, l0 = 0.f, l1 = 0.f;
    float oacc[8][4];
    #pragma unroll
    for (int nb = 0; nb < 8; nb++)
        #pragma unroll
        for (int e = 0; e < 4; e++) oacc[nb][e] = 0.f;

    const int row0 = qt * 64 + wid * 16 + g;

    // ldmatrix lane offsets (halfs)
    const int a_off = (wid * 16 + (lane & 15)) * FPADH + ((lane & 16) ? 8 : 0);   // Q A-frag
    const int p_off = (lane & 15) * FPADH + ((lane & 16) ? 8 : 0);                // P A-frag
    const int kb_off = ((lane & 7) + ((lane & 16) ? 8 : 0)) * FPADH
                     + ((lane & 8) ? 8 : 0);                                      // K B-frag
    const int vb_off = ((lane & 7) + ((lane & 8) ? 8 : 0)) * FPADH
                     + ((lane & 16) ? 8 : 0);                                     // V B-frag (trans)

    for (int kt = 0; kt <= qt; kt++) {
        __syncthreads();
        {
            const int r = tid >> 1, c0 = (tid & 1) * 32;
            const __half* ksrc = Kg + ((size_t)(kt * 64 + r)) * QKVLD + c0;
            const __half* vsrc = Vg + ((size_t)(kt * 64 + r)) * QKVLD + c0;
            __half* kdst = Ks + r * FPADH + c0;
            __half* vdst = Vs + r * FPADH + c0;
            #pragma unroll
            for (int c = 0; c < 32; c += 8) {
                *(uint4*)(kdst + c) = *(const uint4*)(ksrc + c);
                *(uint4*)(vdst + c) = *(const uint4*)(vsrc + c);
            }
        }
        __syncthreads();

        // S = Q @ K^T : 4 k16 steps over d=64
        float sacc[8][4];
        #pragma unroll
        for (int nb = 0; nb < 8; nb++)
            #pragma unroll
            for (int e = 0; e < 4; e++) sacc[nb][e] = 0.f;

        #pragma unroll
        for (int ks = 0; ks < 4; ks++) {
            uint32_t af[4];
            ldm_x4(af, qs_b + (uint32_t)(a_off + ks * 16) * 2);
            #pragma unroll
            for (int np = 0; np < 4; np++) {
                uint32_t t4[4];
                ldm_x4(t4, ks_b + (uint32_t)(kb_off + np * 16 * FPADH + ks * 16) * 2);
                mma_f16(sacc[np * 2 + 0], af, t4);
                mma_f16(sacc[np * 2 + 1], af, t4 + 2);
            }
        }

        const float scale = 0.125f;
        #pragma unroll
        for (int nb = 0; nb < 8; nb++)
            #pragma unroll
            for (int e = 0; e < 4; e++) sacc[nb][e] *= scale;
        if (kt == qt) {
            #pragma unroll
            for (int nb = 0; nb < 8; nb++) {
                const int col = kt * 64 + nb * 8 + tg * 2;
                if (col     > row0) sacc[nb][0] = -1e9f;
                if (col + 1 > row0) sacc[nb][1] = -1e9f;
                if (col     > row0 + 8) sacc[nb][2] = -1e9f;
                if (col + 1 > row0 + 8) sacc[nb][3] = -1e9f;
            }
        }

        float tmax0 = -1e30f, tmax1 = -1e30f;
        #pragma unroll
        for (int nb = 0; nb < 8; nb++) {
            tmax0 = fmaxf(tmax0, fmaxf(sacc[nb][0], sacc[nb][1]));
            tmax1 = fmaxf(tmax1, fmaxf(sacc[nb][2], sacc[nb][3]));
        }
        tmax0 = fmaxf(tmax0, __shfl_xor_sync(0xffffffff, tmax0, 1));
        tmax0 = fmaxf(tmax0, __shfl_xor_sync(0xffffffff, tmax0, 2));
        tmax1 = fmaxf(tmax1, __shfl_xor_sync(0xffffffff, tmax1, 1));
        tmax1 = fmaxf(tmax1, __shfl_xor_sync(0xffffffff, tmax1, 2));

        const float mn0 = fmaxf(m0, tmax0);
        const float mn1 = fmaxf(m1, tmax1);
        const float a0 = __expf(m0 - mn0);
        const float a1 = __expf(m1 - mn1);
        m0 = mn0; m1 = mn1;

        float sum0 = 0.f, sum1 = 0.f;
        __half* Pw = Ps + wid * 16 * FPADH;
        #pragma unroll
        for (int nb = 0; nb < 8; nb++) {
            float p00 = __expf(sacc[nb][0] - mn0);
            float p01 = __expf(sacc[nb][1] - mn0);
            float p10 = __expf(sacc[nb][2] - mn1);
            float p11 = __expf(sacc[nb][3] - mn1);
            sum0 += p00 + p01;
            sum1 += p10 + p11;
            *(uint32_t*)(Pw + g * FPADH + nb * 8 + tg * 2)       = pack_h2(p00, p01);
            *(uint32_t*)(Pw + (g + 8) * FPADH + nb * 8 + tg * 2) = pack_h2(p10, p11);
        }
        sum0 += __shfl_xor_sync(0xffffffff, sum0, 1);
        sum0 += __shfl_xor_sync(0xffffffff, sum0, 2);
        sum1 += __shfl_xor_sync(0xffffffff, sum1, 1);
        sum1 += __shfl_xor_sync(0xffffffff, sum1, 2);
        l0 = l0 * a0 + sum0;
        l1 = l1 * a1 + sum1;

        #pragma unroll
        for (int nb = 0; nb < 8; nb++) {
            oacc[nb][0] *= a0; oacc[nb][1] *= a0;
            oacc[nb][2] *= a1; oacc[nb][3] *= a1;
        }

        __syncwarp();

        // O += P @ V : 4 k16 steps over kv=64; V B-frags via ldmatrix.trans
        #pragma unroll
        for (int kb = 0; kb < 4; kb++) {
            uint32_t pf[4];
            ldm_x4(pf, pw_b + (uint32_t)(p_off + kb * 16) * 2);
            #pragma unroll
            for (int np = 0; np < 4; np++) {
                uint32_t t4[4];
                ldm_x4t(t4, vs_b + (uint32_t)(vb_off + kb * 16 * FPADH + np * 16) * 2);
                mma_f16(oacc[np * 2 + 0], pf, t4);
                mma_f16(oacc[np * 2 + 1], pf, t4 + 2);
            }
        }
    }

    const float inv0 = 1.f / l0;
    const float inv1 = 1.f / l1;
    __half* orow0 = g_oh + ((size_t)b * SEQ + row0    ) * DIM + hh * HSZ;
    __half* orow1 = g_oh + ((size_t)b * SEQ + row0 + 8) * DIM + hh * HSZ;
    #pragma unroll
    for (int nb = 0; nb < 8; nb++) {
        const int c = nb * 8 + tg * 2;
        *(uint32_t*)(orow0 + c) = pack_h2(oacc[nb][0] * inv0, oacc[nb][1] * inv0);
        *(uint32_t*)(orow1 + c) = pack_h2(oacc[nb][2] * inv1, oacc[nb][3] * inv1);
    }
}

// ------- fused QKV weight transpose: [L,H,D,HS] x3 -> wqkvT [L][3][H*HS][D] --
__global__ __launch_bounds__(256)
void tqkv_kernel(const float* __restrict__ Wq, const float* __restrict__ Wk,
                 const float* __restrict__ Wv) {
    __shared__ float t[32][33];
    const long long DD = (long long)DIM * DIM;
    int z = blockIdx.z;
    int part = z / (NL * NH);
    int rest = z % (NL * NH);
    int l = rest / NH, h = rest % NH;
    const float* in = (part == 0 ? Wq : part == 1 ? Wk : Wv)
                      + (long long)rest * DIM * HSZ;
    __half* out = g_wqkvT + (long long)l * 3 * DD + (long long)part * DD
                + (long long)h * HSZ * DIM;
    int c0 = blockIdx.x * 32, r0 = blockIdx.y * 32;
    int tx = threadIdx.x & 31, ty = threadIdx.x >> 5;
    #pragma unroll
    for (int i = 0; i < 4; i++)
        t[ty + i * 8][tx] = in[(long long)(r0 + ty + i * 8) * HSZ + c0 + tx];
    __syncthreads();
    #pragma unroll
    for (int i = 0; i < 4; i++)
        out[(long long)(c0 + ty + i * 8) * DIM + r0 + tx] = __float2half_rn(t[tx][ty + i * 8]);
}

// ------- generic tiled transpose fp32 -> fp16 --------------------------------
__global__ __launch_bounds__(256)
void transpose_kernel(const float* __restrict__ in, __half* __restrict__ out,
                      int R, int C) {
    __shared__ float t[32][33];
    long long z = blockIdx.z;
    in  += z * (long long)R * C;
    out += z * (long long)R * C;
    int c0 = blockIdx.x * 32, r0 = blockIdx.y * 32;
    int tx = threadIdx.x & 31, ty = threadIdx.x >> 5;
    #pragma unroll
    for (int i = 0; i < 4; i++)
        t[ty + i * 8][tx] = in[(long long)(r0 + ty + i * 8) * C + c0 + tx];
    __syncthreads();
    #pragma unroll
    for (int i = 0; i < 4; i++)
        out[(long long)(c0 + ty + i * 8) * R + r0 + tx] = __float2half_rn(t[tx][ty + i * 8]);
}

// ---------------- embedding: fp32 x + fp16 xr --------------------------------
__global__ void embed_kernel(const int* __restrict__ index,
                             const float* __restrict__ tok,
                             const float* __restrict__ pos) {
    int i = blockIdx.x * blockDim.x + threadIdx.x;
    if (i >= MROWS * DIM) return;
    int d = i % DIM;
    int bt = i / DIM;
    int t = bt % SEQ;
    float v = tok[(long long)index[bt] * DIM + d] + pos[(long long)t * DIM + d];
    g_x[i] = v;
    g_xrh[i] = __float2half_rn(v);
}

// ---------------- fp32 SGEMM (LM head only) ----------------------------------
#define BM 64
#define BN 64
#define BKK 16

__global__ __launch_bounds__(256)
void gemm_kernel(const float* __restrict__ A, const float* __restrict__ Bm,
                 const float* __restrict__ bias, float* __restrict__ C,
                 int M, int N, int K, int lda, int ldb, int ldc)
{
    int bm = blockIdx.y * BM;
    int bn = blockIdx.x * BN;
    __shared__ float As[BKK][BM + 1];
    __shared__ float Bs[BKK][BN + 1];

    int tid = threadIdx.x;
    int tx = tid & 15, ty = tid >> 4;
    float acc[4][4] = {};

    for (int k0 = 0; k0 < K; k0 += BKK) {
        #pragma unroll
        for (int i = 0; i < 4; i++) {
            int idx = tid + i * 256;
            int m  = idx >> 4;
            int kk = idx & 15;
            int gm = bm + m;
            float v = 0.f;
            if (gm < M) v = A[(long long)gm * lda + (k0 + kk)];
            As[kk][m] = v;
        }
        #pragma unroll
        for (int i = 0; i < 4; i++) {
            int idx = tid + i * 256;
            int kk = idx >> 6;
            int n  = idx & 63;
            int gn = bn + n;
            float v = 0.f;
            if (gn < N) v = Bm[(long long)(k0 + kk) * ldb + gn];
            Bs[kk][n] = v;
        }
        __syncthreads();
        #pragma unroll
        for (int kk = 0; kk < BKK; kk++) {
            float a[4], b[4];
            #pragma unroll
            for (int i = 0; i < 4; i++) a[i] = As[kk][ty * 4 + i];
            #pragma unroll
            for (int j = 0; j < 4; j++) b[j] = Bs[kk][tx * 4 + j];
            #pragma unroll
            for (int i = 0; i < 4; i++)
                #pragma unroll
                for (int j = 0; j < 4; j++)
                    acc[i][j] += a[i] * b[j];
        }
        __syncthreads();
    }

    #pragma unroll
    for (int i = 0; i < 4; i++) {
        int gm = bm + ty * 4 + i;
        if (gm >= M) continue;
        #pragma unroll
        for (int j = 0; j < 4; j++) {
            int gn = bn + tx * 4 + j;
            if (gn >= N) continue;
            float v = acc[i][j];
            if (bias) v += bias[gn];
            C[(long long)gm * ldc + gn] = v;
        }
    }
}

// -- x = LayerNorm(x (+ y)) * g + b; float4-vectorized; fp16 copy optional ----
__global__ __launch_bounds__(256)
void add_ln_kernel(float* __restrict__ x, const float* __restrict__ y,
                   const float* __restrict__ g, const float* __restrict__ bb,
                   __half* __restrict__ xr) {
    int row = blockIdx.x;
    float* xp = x + (long long)row * DIM;
    const float* yr = y ? y + (long long)row * DIM : nullptr;
    __half* xq = xr ? xr + (long long)row * DIM : nullptr;
    __shared__ float red[256];
    int tid = threadIdx.x;
    const int d = tid * 4;

    float4 v = *(const float4*)(xp + d);
    if (yr) {
        float4 yv = *(const float4*)(yr + d);
        v.x += yv.x; v.y += yv.y; v.z += yv.z; v.w += yv.w;
    }

    red[tid] = v.x + v.y + v.z + v.w;
    __syncthreads();
    for (int st = 128; st > 0; st >>= 1) {
        if (tid < st) red[tid] += red[tid + st];
        __syncthreads();
    }
    float mean = red[0] * (1.0f / DIM);
    __syncthreads();

    float4 c = make_float4(v.x - mean, v.y - mean, v.z - mean, v.w - mean);
    red[tid] = c.x * c.x + c.y * c.y + c.z * c.z + c.w * c.w;
    __syncthreads();
    for (int st = 128; st > 0; st >>= 1) {
        if (tid < st) red[tid] += red[tid + st];
        __syncthreads();
    }
    float inv = rsqrtf(red[0] * (1.0f / DIM) + 1e-5f);

    float4 gv = *(const float4*)(g + d);
    float4 bv = *(const float4*)(bb + d);
    float4 o;
    o.x = c.x * inv * gv.x + bv.x;
    o.y = c.y * inv * gv.y + bv.y;
    o.z = c.z * inv * gv.z + bv.z;
    o.w = c.w * inv * gv.w + bv.w;
    *(float4*)(xp + d) = o;
    if (xq) {
        uint2 h;
        h.x = pack_h2(o.x, o.y);
        h.y = pack_h2(o.z, o.w);
        *(uint2*)(xq + d) = h;
    }
}

// ---------------- per-row NLL + loss -----------------------------------------
__global__ __launch_bounds__(128)
void nll_kernel(const float* __restrict__ logits, const int* __restrict__ targets) {
    int row = blockIdx.x;
    const float* p = logits + (long long)row * VOCABN;
    __shared__ float red[128];
    int tid = threadIdx.x;

    float v = (tid < VOCABN) ? p[tid] : -1e30f;
    red[tid] = v; __syncthreads();
    for (int s = 64; s > 0; s >>= 1) {
        if (tid < s) red[tid] = fmaxf(red[tid], red[tid + s]);
        __syncthreads();
    }
    float m = red[0]; __syncthreads();

    float e = (tid < VOCABN) ? expf(v - m) : 0.f;
    red[tid] = e; __syncthreads();
    for (int s = 64; s > 0; s >>= 1) {
        if (tid < s) red[tid] += red[tid + s];
        __syncthreads();
    }
    if (tid == 0) {
        float lse = m + logf(red[0]);
        g_nll[row] = lse - p[targets[row]];
    }
}

__global__ __launch_bounds__(256)
void loss_kernel(float* __restrict__ out) {
    __shared__ float red[256];
    int tid = threadIdx.x;
    float s = 0.f;
    for (int i = tid; i < MROWS; i += 256) s += g_nll[i];
    red[tid] = s; __syncthreads();
    for (int st = 128; st > 0; st >>= 1) {
        if (tid < st) red[tid] += red[tid + st];
        __syncthreads();
    }
    if (tid == 0) out[0] = red[0] * (1.0f / MROWS);
}

// ---------------- host-side launch helpers ----------------------------------
static void* symv(const void* s) {
    void* p = nullptr;
    cudaGetSymbolAddress(&p, s);
    return p;
}

static void run_gemm_tc(const __half* A, const __half* Bt, const float* bias,
                        float* Cf, __half* Ch,
                        int M, int N, int K, int lda, int ldb, int ldc, int relu) {
    dim3 grid(N / TBN, M / TBM);
    gemm_mma<<<grid, 256, GSM_BYTES>>>(A, Bt, bias, Cf, Ch, K, lda, ldb, ldc, relu);
}

extern "C" void kernel_launch(void* const* d_in, const int* in_sizes, int n_in,
                              void* d_out, int out_size) {
    const int*   index   = (const int*)  d_in[0];
    const int*   targets = (const int*)  d_in[1];
    const float* tok     = (const float*)d_in[2];
    const float* pos     = (const float*)d_in[3];
    const float* Wq      = (const float*)d_in[4];
    const float* Wk      = (const float*)d_in[5];
    const float* Wv      = (const float*)d_in[6];
    const float* Wo      = (const float*)d_in[7];
    const float* bo      = (const float*)d_in[8];
    const float* W1      = (const float*)d_in[9];
    const float* b1      = (const float*)d_in[10];
    const float* W2      = (const float*)d_in[11];
    const float* b2      = (const float*)d_in[12];
    const float* ln1g    = (const float*)d_in[13];
    const float* ln1b    = (const float*)d_in[14];
    const float* ln2g    = (const float*)d_in[15];
    const float* ln2b    = (const float*)d_in[16];
    const float* lnfg    = (const float*)d_in[17];
    const float* lnfb    = (const float*)d_in[18];
    const float* Wlm     = (const float*)d_in[19];
    const float* blm     = (const float*)d_in[20];
    float* out = (float*)d_out;

    float*  x    = (float*) symv(g_x);
    float*  y    = (float*) symv(g_y);
    __half* xrh  = (__half*)symv(g_xrh);
    __half* qkv  = (__half*)symv(g_qkv);
    __half* oh   = (__half*)symv(g_oh);
    __half* hh   = (__half*)symv(g_hh);
    __half* wqkvT= (__half*)symv(g_wqkvT);
    __half* woT  = (__half*)symv(g_woT);
    __half* w1T  = (__half*)symv(g_w1T);
    __half* w2T  = (__half*)symv(g_w2T);

    static int attr_done = 0;
    if (!attr_done) {
        cudaFuncSetAttribute(flash_kernel,
                             cudaFuncAttributeMaxDynamicSharedMemorySize, FA_SMEM);
        cudaFuncSetAttribute(gemm_mma,
                             cudaFuncAttributeMaxDynamicSharedMemorySize, GSM_BYTES);
        attr_done = 1;
    }

    // ---- weight transposes -> [N,K] fp16 ------------------------------------
    {
        dim3 gq(HSZ / 32, DIM / 32, 3 * NL * NH);
        tqkv_kernel<<<gq, 256>>>(Wq, Wk, Wv);
        dim3 g2(DIM / 32, DIM / 32, NL);
        transpose_kernel<<<g2, 256>>>(Wo, woT, DIM, DIM);
        dim3 g3(FFD / 32, DIM / 32, NL);
        transpose_kernel<<<g3, 256>>>(W1, w1T, DIM, FFD);
        dim3 g4(DIM / 32, FFD / 32, NL);
        transpose_kernel<<<g4, 256>>>(W2, w2T, FFD, DIM);
    }

    // embedding
    {
        int n = MROWS * DIM;
        embed_kernel<<<(n + 255) / 256, 256>>>(index, tok, pos);
    }

    for (int l = 0; l < NL; l++) {
        const __half* wqkvT_l = wqkvT + (long long)l * 3 * DIM * DIM;
        const __half* woT_l   = woT   + (long long)l * DIM * DIM;
        const float*  bo_l    = bo    + (long long)l * DIM;
        const __half* w1T_l   = w1T   + (long long)l * DIM * FFD;
        const float*  b1_l    = b1    + (long long)l * FFD;
        const __half* w2T_l   = w2T   + (long long)l * FFD * DIM;
        const float*  b2_l    = b2    + (long long)l * DIM;

        // fused qkv projection -> fp16 (feeds flash)
        run_gemm_tc(xrh, wqkvT_l, nullptr, nullptr, qkv,
                    MROWS, QKVLD, DIM, DIM, DIM, QKVLD, 0);

        // fused causal attention -> g_oh (fp16)
        {
            dim3 grid(SEQ / 64, BATCH * NH);
            flash_kernel<<<grid, 128, FA_SMEM>>>();
        }

        // output projection (fp32 y) + residual LN
        run_gemm_tc(oh, woT_l, bo_l, y, nullptr,
                    MROWS, DIM, DIM, DIM, DIM, DIM, 0);
        add_ln_kernel<<<MROWS, 256>>>(x, y, ln1g + (long long)l * DIM,
                                            ln1b + (long long)l * DIM, xrh);

        // feed-forward: h fp16 (feeds ff2), y fp32 + residual LN
        run_gemm_tc(xrh, w1T_l, b1_l, nullptr, hh,
                    MROWS, FFD, DIM, DIM, DIM, FFD, 1);
        run_gemm_tc(hh, w2T_l, b2_l, y, nullptr,
                    MROWS, DIM, FFD, FFD, FFD, DIM, 0);
        add_ln_kernel<<<MROWS, 256>>>(x, y, ln2g + (long long)l * DIM,
                                            ln2b + (long long)l * DIM, xrh);
    }

    // final LN (no residual, fp32 only — feeds fp32 LM head)
    add_ln_kernel<<<MROWS, 256>>>(x, nullptr, lnfg, lnfb, nullptr);

    // logits = xf @ Wlm + blm (N=96, fp32 path)
    {
        dim3 grid((VOCABN + BN - 1) / BN, MROWS / BM);
        gemm_kernel<<<grid, 256>>>(x, Wlm, blm, out,
                                   MROWS, VOCABN, DIM, DIM, VOCABN, VOCABN);
    }

    // loss
    nll_kernel<<<MROWS, 128>>>(out, targets);
    if (out_size > MROWS * VOCABN) {
        loss_kernel<<<1, 256>>>(out + (long long)MROWS * VOCABN);
    }
}

// round 11
// speedup vs baseline: 1.0910x; 1.0910x over previous
#include <cuda_runtime.h>
#include <cuda_fp16.h>
#include <math.h>
#include <stdint.h>

#define VOCABN 96
#define DIM 1024
#define NH 16
#define HSZ 64
#define NL 8
#define BATCH 8
#define SEQ 1024
#define FFD 4096
#define MROWS (BATCH*SEQ)   // 8192
#define QKVLD (3*DIM)       // fused qkv row stride

// ---------------- scratch (device globals; no allocations allowed) ----------
__device__ float g_x[MROWS*DIM];                       // residual stream fp32
__device__ float g_y[MROWS*DIM];                       // proj/ff2 output fp32
__device__ float g_nll[MROWS];
__device__ __align__(16) __half g_xrh[MROWS*DIM];      // fp16 copy of x
__device__ __align__(16) __half g_qkv[(long long)MROWS*QKVLD];
__device__ __align__(16) __half g_oh[MROWS*DIM];       // attention out fp16
__device__ __align__(16) __half g_hh[(long long)MROWS*FFD];
__device__ __align__(16) __half g_wqkvT[(long long)NL*3*DIM*DIM];
__device__ __align__(16) __half g_woT[NL*DIM*DIM];
__device__ __align__(16) __half g_w1T[(long long)NL*DIM*FFD];
__device__ __align__(16) __half g_w2T[(long long)NL*FFD*DIM];

// ======================= fp16 mma.sync helpers ===============================
__device__ __forceinline__ void mma_f16(float* c, const uint32_t* a, const uint32_t* b) {
    asm volatile(
        "mma.sync.aligned.m16n8k16.row.col.f32.f16.f16.f32 "
        "{%0,%1,%2,%3}, {%4,%5,%6,%7}, {%8,%9}, {%0,%1,%2,%3};"
        : "+f"(c[0]), "+f"(c[1]), "+f"(c[2]), "+f"(c[3])
        : "r"(a[0]), "r"(a[1]), "r"(a[2]), "r"(a[3]),
          "r"(b[0]), "r"(b[1]));
}

__device__ __forceinline__ void ldm_x4(uint32_t* r, uint32_t addr) {
    asm volatile(
        "ldmatrix.sync.aligned.m8n8.x4.shared.b16 {%0,%1,%2,%3}, [%4];"
        : "=r"(r[0]), "=r"(r[1]), "=r"(r[2]), "=r"(r[3]) : "r"(addr));
}

__device__ __forceinline__ void ldm_x4t(uint32_t* r, uint32_t addr) {
    asm volatile(
        "ldmatrix.sync.aligned.m8n8.x4.trans.shared.b16 {%0,%1,%2,%3}, [%4];"
        : "=r"(r[0]), "=r"(r[1]), "=r"(r[2]), "=r"(r[3]) : "r"(addr));
}

__device__ __forceinline__ uint32_t smem_u32_of(const void* p) {
    uint32_t a;
    asm("{ .reg .u64 t; cvta.to.shared.u64 t, %1; cvt.u32.u64 %0, t; }"
        : "=r"(a) : "l"(p));
    return a;
}

__device__ __forceinline__ void cp16(uint32_t dst, const void* src) {
    asm volatile("cp.async.cg.shared.global [%0], [%1], 16;"
                 :: "r"(dst), "l"(src) : "memory");
}

__device__ __forceinline__ uint32_t pack_h2(float a, float b) {
    __half2 h = __floats2half2_rn(a, b);
    return *(uint32_t*)&h;
}

// ============ fp16 tensor GEMM: C[M,N] = A[M,K] @ B^T  (B stored [N,K]) =====
// CTA tile 128x128x32, 256 threads = 8 warps (2m x 4n), warp tile 64x32.
// 2-stage cp.async pipeline; fragments via ldmatrix; fp32 accumulate.
// (round-9 proven config)
#define TBM 128
#define TBN 128
#define TBK 32            // 32 halfs = 2 k16 steps
#define SPADH 40          // smem row stride in halfs
#define GBUFH (128*SPADH) // halfs per tile
#define GSM_BYTES (2*2*GBUFH*2)   // 40960 bytes

__global__ void __launch_bounds__(256, 2)
gemm_mma(const __half* __restrict__ A, const __half* __restrict__ B,
         const float* __restrict__ bias, float* __restrict__ Cf,
         __half* __restrict__ Ch,
         int K, int lda, int ldb, int ldc, int relu)
{
    extern __shared__ __half smh[];
    const int tid  = threadIdx.x;
    const int wid  = tid >> 5;
    const int lane = tid & 31;
    const int g    = lane >> 2;
    const int tg   = lane & 3;
    const int wm   = wid >> 2;    // 0..1
    const int wn   = wid & 3;     // 0..3

    const int bm = blockIdx.y * TBM;
    const int bn = blockIdx.x * TBN;

    // cp.async: thread owns one half-row chunk (16 halfs = 32B)
    const int r = tid >> 1;
    const int ho = (tid & 1) * 16;
    const int rowoff = r * SPADH + ho;

    const uint32_t smb = smem_u32_of(smh);
    const __half* ga = A + (size_t)(bm + r) * lda + ho;
    const __half* gb = B + (size_t)(bn + r) * ldb + ho;

    // ldmatrix per-lane offsets (halfs) relative to tile base
    const int arow = (wm * 64 + (lane & 15)) * SPADH + ((lane & 16) ? 8 : 0);
    const int brow = ((lane & 7) + ((lane & 16) ? 8 : 0)) * SPADH
                   + ((lane & 8) ? 8 : 0);

    float acc[4][4][4] = {};
    const int KT = K / TBK;

    auto issue = [&](int kt, int buf) {
        const __half* pa = ga + (size_t)kt * TBK;
        const __half* pb = gb + (size_t)kt * TBK;
        uint32_t da = smb + (uint32_t)(buf * 2 * GBUFH + rowoff) * 2;
        uint32_t db = da + GBUFH * 2;
        cp16(da,      pa);
        cp16(da + 16, pa + 8);
        cp16(db,      pb);
        cp16(db + 16, pb + 8);
        asm volatile("cp.async.commit_group;" ::: "memory");
    };

    issue(0, 0);

    int buf = 0;
    for (int kt = 0; kt < KT; kt++) {
        asm volatile("cp.async.wait_group 0;" ::: "memory");
        __syncthreads();
        if (kt + 1 < KT) issue(kt + 1, buf ^ 1);

        const uint32_t abase = smb + (uint32_t)(buf * 2 * GBUFH + arow) * 2;
        const uint32_t bbase = smb + (uint32_t)(buf * 2 * GBUFH + GBUFH + brow) * 2;

        #pragma unroll
        for (int ks = 0; ks < 2; ks++) {          // k16 steps
            uint32_t af[4][4], bf[4][2];
            #pragma unroll
            for (int i = 0; i < 4; i++)
                ldm_x4(af[i], abase + (uint32_t)(i * 16 * SPADH + ks * 16) * 2);
            #pragma unroll
            for (int np = 0; np < 2; np++) {      // n 16-blocks within warp's 32
                uint32_t t4[4];
                ldm_x4(t4, bbase + (uint32_t)((wn * 32 + np * 16) * SPADH + ks * 16) * 2);
                bf[np * 2 + 0][0] = t4[0]; bf[np * 2 + 0][1] = t4[1];
                bf[np * 2 + 1][0] = t4[2]; bf[np * 2 + 1][1] = t4[3];
            }
            #pragma unroll
            for (int i = 0; i < 4; i++)
                #pragma unroll
                for (int j = 0; j < 4; j++)
                    mma_f16(acc[i][j], af[i], bf[j]);
        }
        buf ^= 1;
    }

    // epilogue: bias + relu; write fp16 (tensor consumers) or fp32 (residual)
    #pragma unroll
    for (int i = 0; i < 4; i++) {
        const int m0 = bm + wm * 64 + i * 16 + g;
        #pragma unroll
        for (int j = 0; j < 4; j++) {
            const int n0 = bn + wn * 32 + j * 8 + tg * 2;
            float2 v0 = make_float2(acc[i][j][0], acc[i][j][1]);
            float2 v1 = make_float2(acc[i][j][2], acc[i][j][3]);
            if (bias) {
                float2 bv = *(const float2*)(bias + n0);
                v0.x += bv.x; v0.y += bv.y;
                v1.x += bv.x; v1.y += bv.y;
            }
            if (relu) {
                v0.x = fmaxf(v0.x, 0.f); v0.y = fmaxf(v0.y, 0.f);
                v1.x = fmaxf(v1.x, 0.f); v1.y = fmaxf(v1.y, 0.f);
            }
            if (Ch) {
                *(uint32_t*)(Ch + (size_t)m0 * ldc + n0)       = pack_h2(v0.x, v0.y);
                *(uint32_t*)(Ch + (size_t)(m0 + 8) * ldc + n0) = pack_h2(v1.x, v1.y);
            } else {
                *(float2*)(Cf + (size_t)m0 * ldc + n0)       = v0;
                *(float2*)(Cf + (size_t)(m0 + 8) * ldc + n0) = v1;
            }
        }
    }
}

// ============ Flash attention (causal, online softmax, fp16 mma) ============
// grid = (8 q-tiles of 128 rows, B*NH). block = 256 threads (8 warps x 16 rows).
// K/V tiles 64 rows -> per-(b,h) smem-fill/sync events drop ~2x vs 64-row Q.
#define FPADH 72
#define FA_SMEM ((128 + 64 + 64 + 128) * FPADH * 2)   // 55296 bytes

__global__ void __launch_bounds__(256, 2)
flash_kernel()
{
    extern __shared__ __half smh[];
    __half* Qs = smh;                    // [128][FPADH]
    __half* Ks = smh + 128 * FPADH;      // [64][FPADH]
    __half* Vs = smh + 192 * FPADH;      // [64][FPADH]
    __half* Ps = smh + 256 * FPADH;      // [8][16][FPADH]

    const int bh = blockIdx.y;
    const int b = bh >> 4, hh = bh & 15;
    const int qt = gridDim.x - 1 - blockIdx.x;   // heavy blocks first
    const int tid = threadIdx.x;
    const int wid = tid >> 5, lane = tid & 31;
    const int g = lane >> 2, tg = lane & 3;

    const __half* Qg = g_qkv + ((size_t)b * SEQ + qt * 128) * QKVLD + hh * HSZ;
    const __half* Kg = g_qkv + (size_t)b * SEQ * QKVLD + DIM + hh * HSZ;
    const __half* Vg = g_qkv + (size_t)b * SEQ * QKVLD + 2 * DIM + hh * HSZ;

    const uint32_t smb = smem_u32_of(smh);
    const uint32_t qs_b = smb;
    const uint32_t ks_b = smb + 128 * FPADH * 2;
    const uint32_t vs_b = smb + 192 * FPADH * 2;
    const uint32_t pw_b = smb + (256 + wid * 16) * FPADH * 2;

    // load Q tile (128 rows x 64 halfs): thread owns half a row
    {
        const int r = tid >> 1, c0 = (tid & 1) * 32;
        const __half* src = Qg + (size_t)r * QKVLD + c0;
        __half* dst = Qs + r * FPADH + c0;
        #pragma unroll
        for (int c = 0; c < 32; c += 8)
            *(uint4*)(dst + c) = *(const uint4*)(src + c);
    }

    float m0 = -1e30f, m1 = -1e30f, l0 = 0.f, l1 = 0.f;
    float oacc[8][4];
    #pragma unroll
    for (int nb = 0; nb < 8; nb++)
        #pragma unroll
        for (int e = 0; e < 4; e++) oacc[nb][e] = 0.f;

    const int row0 = qt * 128 + wid * 16 + g;
    const int wrow = qt * 128 + wid * 16;        // warp's first q row

    // ldmatrix lane offsets (halfs)
    const int a_off = (wid * 16 + (lane & 15)) * FPADH + ((lane & 16) ? 8 : 0);   // Q A-frag
    const int p_off = (lane & 15) * FPADH + ((lane & 16) ? 8 : 0);                // P A-frag
    const int kb_off = ((lane & 7) + ((lane & 16) ? 8 : 0)) * FPADH
                     + ((lane & 8) ? 8 : 0);                                      // K B-frag
    const int vb_off = ((lane & 7) + ((lane & 8) ? 8 : 0)) * FPADH
                     + ((lane & 16) ? 8 : 0);                                     // V B-frag (trans)

    const int KTT = 2 * qt + 2;                  // kv tiles: cols < (qt+1)*128

    for (int kt = 0; kt < KTT; kt++) {
        __syncthreads();
        // load K,V tiles (64 rows x 64 halfs): thread owns quarter-row
        {
            const int r = tid >> 2, c0 = (tid & 3) * 16;
            const __half* ksrc = Kg + ((size_t)(kt * 64 + r)) * QKVLD + c0;
            const __half* vsrc = Vg + ((size_t)(kt * 64 + r)) * QKVLD + c0;
            __half* kdst = Ks + r * FPADH + c0;
            __half* vdst = Vs + r * FPADH + c0;
            *(uint4*)(kdst)     = *(const uint4*)(ksrc);
            *(uint4*)(kdst + 8) = *(const uint4*)(vsrc + 0 - 0 + 8 - 8), // placeholder avoided below
            *(uint4*)(kdst + 8) = *(const uint4*)(ksrc + 8);
            *(uint4*)(vdst)     = *(const uint4*)(vsrc);
            *(uint4*)(vdst + 8) = *(const uint4*)(vsrc + 8);
        }
        __syncthreads();

        // S = Q @ K^T : 4 k16 steps over d=64
        float sacc[8][4];
        #pragma unroll
        for (int nb = 0; nb < 8; nb++)
            #pragma unroll
            for (int e = 0; e < 4; e++) sacc[nb][e] = 0.f;

        #pragma unroll
        for (int ks = 0; ks < 4; ks++) {
            uint32_t af[4];
            ldm_x4(af, qs_b + (uint32_t)(a_off + ks * 16) * 2);
            #pragma unroll
            for (int np = 0; np < 4; np++) {
                uint32_t t4[4];
                ldm_x4(t4, ks_b + (uint32_t)(kb_off + np * 16 * FPADH + ks * 16) * 2);
                mma_f16(sacc[np * 2 + 0], af, t4);
                mma_f16(sacc[np * 2 + 1], af, t4 + 2);
            }
        }

        const float scale = 0.125f;
        #pragma unroll
        for (int nb = 0; nb < 8; nb++)
            #pragma unroll
            for (int e = 0; e < 4; e++) sacc[nb][e] *= scale;

        // causal mask: needed iff this kv tile can reach past the warp's rows
        if (kt * 64 + 63 > wrow) {
            #pragma unroll
            for (int nb = 0; nb < 8; nb++) {
                const int col = kt * 64 + nb * 8 + tg * 2;
                if (col     > row0) sacc[nb][0] = -1e9f;
                if (col + 1 > row0) sacc[nb][1] = -1e9f;
                if (col     > row0 + 8) sacc[nb][2] = -1e9f;
                if (col + 1 > row0 + 8) sacc[nb][3] = -1e9f;
            }
        }

        float tmax0 = -1e30f, tmax1 = -1e30f;
        #pragma unroll
        for (int nb = 0; nb < 8; nb++) {
            tmax0 = fmaxf(tmax0, fmaxf(sacc[nb][0], sacc[nb][1]));
            tmax1 = fmaxf(tmax1, fmaxf(sacc[nb][2], sacc[nb][3]));
        }
        tmax0 = fmaxf(tmax0, __shfl_xor_sync(0xffffffff, tmax0, 1));
        tmax0 = fmaxf(tmax0, __shfl_xor_sync(0xffffffff, tmax0, 2));
        tmax1 = fmaxf(tmax1, __shfl_xor_sync(0xffffffff, tmax1, 1));
        tmax1 = fmaxf(tmax1, __shfl_xor_sync(0xffffffff, tmax1, 2));

        const float mn0 = fmaxf(m0, tmax0);
        const float mn1 = fmaxf(m1, tmax1);
        const float a0 = __expf(m0 - mn0);
        const float a1 = __expf(m1 - mn1);
        m0 = mn0; m1 = mn1;

        float sum0 = 0.f, sum1 = 0.f;
        __half* Pw = Ps + wid * 16 * FPADH;
        #pragma unroll
        for (int nb = 0; nb < 8; nb++) {
            float p00 = __expf(sacc[nb][0] - mn0);
            float p01 = __expf(sacc[nb][1] - mn0);
            float p10 = __expf(sacc[nb][2] - mn1);
            float p11 = __expf(sacc[nb][3] - mn1);
            sum0 += p00 + p01;
            sum1 += p10 + p11;
            *(uint32_t*)(Pw + g * FPADH + nb * 8 + tg * 2)       = pack_h2(p00, p01);
            *(uint32_t*)(Pw + (g + 8) * FPADH + nb * 8 + tg * 2) = pack_h2(p10, p11);
        }
        sum0 += __shfl_xor_sync(0xffffffff, sum0, 1);
        sum0 += __shfl_xor_sync(0xffffffff, sum0, 2);
        sum1 += __shfl_xor_sync(0xffffffff, sum1, 1);
        sum1 += __shfl_xor_sync(0xffffffff, sum1, 2);
        l0 = l0 * a0 + sum0;
        l1 = l1 * a1 + sum1;

        #pragma unroll
        for (int nb = 0; nb < 8; nb++) {
            oacc[nb][0] *= a0; oacc[nb][1] *= a0;
            oacc[nb][2] *= a1; oacc[nb][3] *= a1;
        }

        __syncwarp();

        // O += P @ V : 4 k16 steps over kv=64; V B-frags via ldmatrix.trans
        #pragma unroll
        for (int kb = 0; kb < 4; kb++) {
            uint32_t pf[4];
            ldm_x4(pf, pw_b + (uint32_t)(p_off + kb * 16) * 2);
            #pragma unroll
            for (int np = 0; np < 4; np++) {
                uint32_t t4[4];
                ldm_x4t(t4, vs_b + (uint32_t)(vb_off + kb * 16 * FPADH + np * 16) * 2);
                mma_f16(oacc[np * 2 + 0], pf, t4);
                mma_f16(oacc[np * 2 + 1], pf, t4 + 2);
            }
        }
    }

    const float inv0 = 1.f / l0;
    const float inv1 = 1.f / l1;
    __half* orow0 = g_oh + ((size_t)b * SEQ + row0    ) * DIM + hh * HSZ;
    __half* orow1 = g_oh + ((size_t)b * SEQ + row0 + 8) * DIM + hh * HSZ;
    #pragma unroll
    for (int nb = 0; nb < 8; nb++) {
        const int c = nb * 8 + tg * 2;
        *(uint32_t*)(orow0 + c) = pack_h2(oacc[nb][0] * inv0, oacc[nb][1] * inv0);
        *(uint32_t*)(orow1 + c) = pack_h2(oacc[nb][2] * inv1, oacc[nb][3] * inv1);
    }
}

// ------- fused QKV weight transpose: [L,H,D,HS] x3 -> wqkvT [L][3][H*HS][D] --
__global__ __launch_bounds__(256)
void tqkv_kernel(const float* __restrict__ Wq, const float* __restrict__ Wk,
                 const float* __restrict__ Wv) {
    __shared__ float t[32][33];
    const long long DD = (long long)DIM * DIM;
    int z = blockIdx.z;
    int part = z / (NL * NH);
    int rest = z % (NL * NH);
    int l = rest / NH, h = rest % NH;
    const float* in = (part == 0 ? Wq : part == 1 ? Wk : Wv)
                      + (long long)rest * DIM * HSZ;
    __half* out = g_wqkvT + (long long)l * 3 * DD + (long long)part * DD
                + (long long)h * HSZ * DIM;
    int c0 = blockIdx.x * 32, r0 = blockIdx.y * 32;
    int tx = threadIdx.x & 31, ty = threadIdx.x >> 5;
    #pragma unroll
    for (int i = 0; i < 4; i++)
        t[ty + i * 8][tx] = in[(long long)(r0 + ty + i * 8) * HSZ + c0 + tx];
    __syncthreads();
    #pragma unroll
    for (int i = 0; i < 4; i++)
        out[(long long)(c0 + ty + i * 8) * DIM + r0 + tx] = __float2half_rn(t[tx][ty + i * 8]);
}

// ------- generic tiled transpose fp32 -> fp16 --------------------------------
__global__ __launch_bounds__(256)
void transpose_kernel(const float* __restrict__ in, __half* __restrict__ out,
                      int R, int C) {
    __shared__ float t[32][33];
    long long z = blockIdx.z;
    in  += z * (long long)R * C;
    out += z * (long long)R * C;
    int c0 = blockIdx.x * 32, r0 = blockIdx.y * 32;
    int tx = threadIdx.x & 31, ty = threadIdx.x >> 5;
    #pragma unroll
    for (int i = 0; i < 4; i++)
        t[ty + i * 8][tx] = in[(long long)(r0 + ty + i * 8) * C + c0 + tx];
    __syncthreads();
    #pragma unroll
    for (int i = 0; i < 4; i++)
        out[(long long)(c0 + ty + i * 8) * R + r0 + tx] = __float2half_rn(t[tx][ty + i * 8]);
}

// ---------------- embedding: fp32 x + fp16 xr --------------------------------
__global__ void embed_kernel(const int* __restrict__ index,
                             const float* __restrict__ tok,
                             const float* __restrict__ pos) {
    int i = blockIdx.x * blockDim.x + threadIdx.x;
    if (i >= MROWS * DIM) return;
    int d = i % DIM;
    int bt = i / DIM;
    int t = bt % SEQ;
    float v = tok[(long long)index[bt] * DIM + d] + pos[(long long)t * DIM + d];
    g_x[i] = v;
    g_xrh[i] = __float2half_rn(v);
}

// ---------------- fp32 SGEMM (LM head only) ----------------------------------
#define BM 64
#define BN 64
#define BKK 16

__global__ __launch_bounds__(256)
void gemm_kernel(const float* __restrict__ A, const float* __restrict__ Bm,
                 const float* __restrict__ bias, float* __restrict__ C,
                 int M, int N, int K, int lda, int ldb, int ldc)
{
    int bm = blockIdx.y * BM;
    int bn = blockIdx.x * BN;
    __shared__ float As[BKK][BM + 1];
    __shared__ float Bs[BKK][BN + 1];

    int tid = threadIdx.x;
    int tx = tid & 15, ty = tid >> 4;
    float acc[4][4] = {};

    for (int k0 = 0; k0 < K; k0 += BKK) {
        #pragma unroll
        for (int i = 0; i < 4; i++) {
            int idx = tid + i * 256;
            int m  = idx >> 4;
            int kk = idx & 15;
            int gm = bm + m;
            float v = 0.f;
            if (gm < M) v = A[(long long)gm * lda + (k0 + kk)];
            As[kk][m] = v;
        }
        #pragma unroll
        for (int i = 0; i < 4; i++) {
            int idx = tid + i * 256;
            int kk = idx >> 6;
            int n  = idx & 63;
            int gn = bn + n;
            float v = 0.f;
            if (gn < N) v = Bm[(long long)(k0 + kk) * ldb + gn];
            Bs[kk][n] = v;
        }
        __syncthreads();
        #pragma unroll
        for (int kk = 0; kk < BKK; kk++) {
            float a[4], b[4];
            #pragma unroll
            for (int i = 0; i < 4; i++) a[i] = As[kk][ty * 4 + i];
            #pragma unroll
            for (int j = 0; j < 4; j++) b[j] = Bs[kk][tx * 4 + j];
            #pragma unroll
            for (int i = 0; i < 4; i++)
                #pragma unroll
                for (int j = 0; j < 4; j++)
                    acc[i][j] += a[i] * b[j];
        }
        __syncthreads();
    }

    #pragma unroll
    for (int i = 0; i < 4; i++) {
        int gm = bm + ty * 4 + i;
        if (gm >= M) continue;
        #pragma unroll
        for (int j = 0; j < 4; j++) {
            int gn = bn + tx * 4 + j;
            if (gn >= N) continue;
            float v = acc[i][j];
            if (bias) v += bias[gn];
            C[(long long)gm * ldc + gn] = v;
        }
    }
}

// -- x = LayerNorm(x (+ y)) * g + b; float4-vectorized; fp16 copy optional ----
__global__ __launch_bounds__(256)
void add_ln_kernel(float* __restrict__ x, const float* __restrict__ y,
                   const float* __restrict__ g, const float* __restrict__ bb,
                   __half* __restrict__ xr) {
    int row = blockIdx.x;
    float* xp = x + (long long)row * DIM;
    const float* yr = y ? y + (long long)row * DIM : nullptr;
    __half* xq = xr ? xr + (long long)row * DIM : nullptr;
    __shared__ float red[256];
    int tid = threadIdx.x;
    const int d = tid * 4;

    float4 v = *(const float4*)(xp + d);
    if (yr) {
        float4 yv = *(const float4*)(yr + d);
        v.x += yv.x; v.y += yv.y; v.z += yv.z; v.w += yv.w;
    }

    red[tid] = v.x + v.y + v.z + v.w;
    __syncthreads();
    for (int st = 128; st > 0; st >>= 1) {
        if (tid < st) red[tid] += red[tid + st];
        __syncthreads();
    }
    float mean = red[0] * (1.0f / DIM);
    __syncthreads();

    float4 c = make_float4(v.x - mean, v.y - mean, v.z - mean, v.w - mean);
    red[tid] = c.x * c.x + c.y * c.y + c.z * c.z + c.w * c.w;
    __syncthreads();
    for (int st = 128; st > 0; st >>= 1) {
        if (tid < st) red[tid] += red[tid + st];
        __syncthreads();
    }
    float inv = rsqrtf(red[0] * (1.0f / DIM) + 1e-5f);

    float4 gv = *(const float4*)(g + d);
    float4 bv = *(const float4*)(bb + d);
    float4 o;
    o.x = c.x * inv * gv.x + bv.x;
    o.y = c.y * inv * gv.y + bv.y;
    o.z = c.z * inv * gv.z + bv.z;
    o.w = c.w * inv * gv.w + bv.w;
    *(float4*)(xp + d) = o;
    if (xq) {
        uint2 h;
        h.x = pack_h2(o.x, o.y);
        h.y = pack_h2(o.z, o.w);
        *(uint2*)(xq + d) = h;
    }
}

// ---------------- per-row NLL + loss -----------------------------------------
__global__ __launch_bounds__(128)
void nll_kernel(const float* __restrict__ logits, const int* __restrict__ targets) {
    int row = blockIdx.x;
    const float* p = logits + (long long)row * VOCABN;
    __shared__ float red[128];
    int tid = threadIdx.x;

    float v = (tid < VOCABN) ? p[tid] : -1e30f;
    red[tid] = v; __syncthreads();
    for (int s = 64; s > 0; s >>= 1) {
        if (tid < s) red[tid] = fmaxf(red[tid], red[tid + s]);
        __syncthreads();
    }
    float m = red[0]; __syncthreads();

    float e = (tid < VOCABN) ? expf(v - m) : 0.f;
    red[tid] = e; __syncthreads();
    for (int s = 64; s > 0; s >>= 1) {
        if (tid < s) red[tid] += red[tid + s];
        __syncthreads();
    }
    if (tid == 0) {
        float lse = m + logf(red[0]);
        g_nll[row] = lse - p[targets[row]];
    }
}

__global__ __launch_bounds__(256)
void loss_kernel(float* __restrict__ out) {
    __shared__ float red[256];
    int tid = threadIdx.x;
    float s = 0.f;
    for (int i = tid; i < MROWS; i += 256) s += g_nll[i];
    red[tid] = s; __syncthreads();
    for (int st = 128; st > 0; st >>= 1) {
        if (tid < st) red[tid] += red[tid + st];
        __syncthreads();
    }
    if (tid == 0) out[0] = red[0] * (1.0f / MROWS);
}

// ---------------- host-side launch helpers ----------------------------------
static void* symv(const void* s) {
    void* p = nullptr;
    cudaGetSymbolAddress(&p, s);
    return p;
}

static void run_gemm_tc(const __half* A, const __half* Bt, const float* bias,
                        float* Cf, __half* Ch,
                        int M, int N, int K, int lda, int ldb, int ldc, int relu) {
    dim3 grid(N / TBN, M / TBM);
    gemm_mma<<<grid, 256, GSM_BYTES>>>(A, Bt, bias, Cf, Ch, K, lda, ldb, ldc, relu);
}

extern "C" void kernel_launch(void* const* d_in, const int* in_sizes, int n_in,
                              void* d_out, int out_size) {
    const int*   index   = (const int*)  d_in[0];
    const int*   targets = (const int*)  d_in[1];
    const float* tok     = (const float*)d_in[2];
    const float* pos     = (const float*)d_in[3];
    const float* Wq      = (const float*)d_in[4];
    const float* Wk      = (const float*)d_in[5];
    const float* Wv      = (const float*)d_in[6];
    const float* Wo      = (const float*)d_in[7];
    const float* bo      = (const float*)d_in[8];
    const float* W1      = (const float*)d_in[9];
    const float* b1      = (const float*)d_in[10];
    const float* W2      = (const float*)d_in[11];
    const float* b2      = (const float*)d_in[12];
    const float* ln1g    = (const float*)d_in[13];
    const float* ln1b    = (const float*)d_in[14];
    const float* ln2g    = (const float*)d_in[15];
    const float* ln2b    = (const float*)d_in[16];
    const float* lnfg    = (const float*)d_in[17];
    const float* lnfb    = (const float*)d_in[18];
    const float* Wlm     = (const float*)d_in[19];
    const float* blm     = (const float*)d_in[20];
    float* out = (float*)d_out;

    float*  x    = (float*) symv(g_x);
    float*  y    = (float*) symv(g_y);
    __half* xrh  = (__half*)symv(g_xrh);
    __half* qkv  = (__half*)symv(g_qkv);
    __half* oh   = (__half*)symv(g_oh);
    __half* hh   = (__half*)symv(g_hh);
    __half* wqkvT= (__half*)symv(g_wqkvT);
    __half* woT  = (__half*)symv(g_woT);
    __half* w1T  = (__half*)symv(g_w1T);
    __half* w2T  = (__half*)symv(g_w2T);

    static int attr_done = 0;
    if (!attr_done) {
        cudaFuncSetAttribute(flash_kernel,
                             cudaFuncAttributeMaxDynamicSharedMemorySize, FA_SMEM);
        cudaFuncSetAttribute(gemm_mma,
                             cudaFuncAttributeMaxDynamicSharedMemorySize, GSM_BYTES);
        attr_done = 1;
    }

    // ---- weight transposes -> [N,K] fp16 ------------------------------------
    {
        dim3 gq(HSZ / 32, DIM / 32, 3 * NL * NH);
        tqkv_kernel<<<gq, 256>>>(Wq, Wk, Wv);
        dim3 g2(DIM / 32, DIM / 32, NL);
        transpose_kernel<<<g2, 256>>>(Wo, woT, DIM, DIM);
        dim3 g3(FFD / 32, DIM / 32, NL);
        transpose_kernel<<<g3, 256>>>(W1, w1T, DIM, FFD);
        dim3 g4(DIM / 32, FFD / 32, NL);
        transpose_kernel<<<g4, 256>>>(W2, w2T, FFD, DIM);
    }

    // embedding
    {
        int n = MROWS * DIM;
        embed_kernel<<<(n + 255) / 256, 256>>>(index, tok, pos);
    }

    for (int l = 0; l < NL; l++) {
        const __half* wqkvT_l = wqkvT + (long long)l * 3 * DIM * DIM;
        const __half* woT_l   = woT   + (long long)l * DIM * DIM;
        const float*  bo_l    = bo    + (long long)l * DIM;
        const __half* w1T_l   = w1T   + (long long)l * DIM * FFD;
        const float*  b1_l    = b1    + (long long)l * FFD;
        const __half* w2T_l   = w2T   + (long long)l * FFD * DIM;
        const float*  b2_l    = b2    + (long long)l * DIM;

        // fused qkv projection -> fp16 (feeds flash)
        run_gemm_tc(xrh, wqkvT_l, nullptr, nullptr, qkv,
                    MROWS, QKVLD, DIM, DIM, DIM, QKVLD, 0);

        // fused causal attention -> g_oh (fp16)
        {
            dim3 grid(SEQ / 128, BATCH * NH);
            flash_kernel<<<grid, 256, FA_SMEM>>>();
        }

        // output projection (fp32 y) + residual LN
        run_gemm_tc(oh, woT_l, bo_l, y, nullptr,
                    MROWS, DIM, DIM, DIM, DIM, DIM, 0);
        add_ln_kernel<<<MROWS, 256>>>(x, y, ln1g + (long long)l * DIM,
                                            ln1b + (long long)l * DIM, xrh);

        // feed-forward: h fp16 (feeds ff2), y fp32 + residual LN
        run_gemm_tc(xrh, w1T_l, b1_l, nullptr, hh,
                    MROWS, FFD, DIM, DIM, DIM, FFD, 1);
        run_gemm_tc(hh, w2T_l, b2_l, y, nullptr,
                    MROWS, DIM, FFD, FFD, FFD, DIM, 0);
        add_ln_kernel<<<MROWS, 256>>>(x, y, ln2g + (long long)l * DIM,
                                            ln2b + (long long)l * DIM, xrh);
    }

    // final LN (no residual, fp32 only — feeds fp32 LM head)
    add_ln_kernel<<<MROWS, 256>>>(x, nullptr, lnfg, lnfb, nullptr);

    // logits = xf @ Wlm + blm (N=96, fp32 path)
    {
        dim3 grid((VOCABN + BN - 1) / BN, MROWS / BM);
        gemm_kernel<<<grid, 256>>>(x, Wlm, blm, out,
                                   MROWS, VOCABN, DIM, DIM, VOCABN, VOCABN);
    }

    // loss
    nll_kernel<<<MROWS, 128>>>(out, targets);
    if (out_size > MROWS * VOCABN) {
        loss_kernel<<<1, 256>>>(out + (long long)MROWS * VOCABN);
    }
}